// round 9
// baseline (speedup 1.0000x reference)
#include <cuda_runtime.h>
#include <cuda_bf16.h>
#include <cstdint>

// MX e4m3 quantize-dequantize, block size 32 along rows.
// Grid-stride software-pipelined: each thread prefetches the next tile's
// 2 float4 before computing/storing the current tile, keeping loads
// outstanding through the compute phase (steady HBM R/W interleave).
// Coalesced: lane l handles float4 (tileBase + i*32 + l); one MX block =
// one aligned 8-lane group at fixed i. Numerics identical to prior rounds.

__device__ __forceinline__ float mx_scale(float amax) {
    // sc = bf16(RN(amax/448)) ; RN division via Markstein with r448=RN(1/448)
    const float r448 = 1.0f / 448.0f;
    float q0 = __fmul_rn(amax, r448);
    float dv = __fmaf_rn(__fmaf_rn(-q0, 448.0f, amax), r448, q0);
    float sc = __bfloat162float(__float2bfloat16(dv));
    // s = floor_bf16(sc*256 + 0.5) * 2^-8 (bf16 semantics), 0 -> 1
    float t = sc * 256.0f;                                   // exact exp shift
    float u = __bfloat162float(__float2bfloat16(t + 0.5f));  // bf16 add (RN)
    float s = floorf(u) * 0.00390625f;                       // exact * 2^-8
    return (s == 0.0f) ? 1.0f : s;
}

__device__ __forceinline__ float qdq_e4m3(float x, float s, float r,
                                          uint32_t sB, float c448s) {
    // correctly-rounded d = x / s (Markstein, r = RN(1/s))
    float q0 = __fmul_rn(x, r);
    float d  = __fmaf_rn(__fmaf_rn(-q0, s, x), r, q0);

    uint32_t db  = __float_as_uint(d);
    uint32_t mb  = db & 0x7FFFFFFFu;                       // |d|
    uint32_t peb = max(mb & 0x7F800000u, 0x3C800000u);     // 2^e, e>=-6
    float inv = __uint_as_float(0x80800000u - peb);        // 2^(3-e)
    float ps  = __uint_as_float(peb + sB);                 // 2^(e-3)*s (exact)
    float q = floorf(__fmaf_rn(__uint_as_float(mb), inv, 0.5f)); // half-away
    float outmag = fminf(__fmul_rn(q, ps), c448s);         // == min(q*pout,448)*s
    return __uint_as_float(__float_as_uint(outmag) | (db & 0x80000000u));
}

__device__ __forceinline__ float4 qdq_vec(float4 v, float s, float r,
                                          uint32_t sB, float c448s) {
    float4 o;
    o.x = qdq_e4m3(v.x, s, r, sB, c448s);
    o.y = qdq_e4m3(v.y, s, r, sB, c448s);
    o.z = qdq_e4m3(v.z, s, r, sB, c448s);
    o.w = qdq_e4m3(v.w, s, r, sB, c448s);
    return o;
}

__device__ __forceinline__ void block_scale(float4 v, float& s, float& r,
                                            uint32_t& sB, float& c448s) {
    float m = fmaxf(fmaxf(fabsf(v.x), fabsf(v.y)),
                    fmaxf(fabsf(v.z), fabsf(v.w)));
    m = fmaxf(m, __shfl_xor_sync(0xFFFFFFFFu, m, 1));
    m = fmaxf(m, __shfl_xor_sync(0xFFFFFFFFu, m, 2));
    m = fmaxf(m, __shfl_xor_sync(0xFFFFFFFFu, m, 4));
    s = mx_scale(m);
    r = 1.0f / s;                              // RN reciprocal per block
    sB = __float_as_uint(s) - 0x41000000u;     // fold *2^-3 * s
    c448s = 448.0f * s;                        // exact
}

__global__ void __launch_bounds__(256)
mxq_kernel(const float4* __restrict__ x, float4* __restrict__ y, int nf4) {
    int lane = threadIdx.x & 31;
    int gwarp = (blockIdx.x * blockDim.x + threadIdx.x) >> 5;
    int warps_total = (gridDim.x * blockDim.x) >> 5;
    size_t stride = (size_t)warps_total * 64;        // float4 per grid iteration
    size_t p = (size_t)gwarp * 64 + lane;

    if ((size_t)gwarp * 64 >= (size_t)nf4) return;

    float4 a0 = __ldcs(x + p);
    float4 a1 = __ldcs(x + p + 32);

    for (;;) {
        size_t np = p + stride;
        bool more = (np - (size_t)lane) < (size_t)nf4;   // warp-uniform
        float4 b0, b1;
        if (more) {                        // prefetch next tile before compute
            b0 = __ldcs(x + np);
            b1 = __ldcs(x + np + 32);
        }

        float s0, r0, c0; uint32_t B0;
        float s1, r1, c1; uint32_t B1;
        block_scale(a0, s0, r0, B0, c0);
        block_scale(a1, s1, r1, B1, c1);
        __stcs(y + p,      qdq_vec(a0, s0, r0, B0, c0));
        __stcs(y + p + 32, qdq_vec(a1, s1, r1, B1, c1));

        if (!more) break;
        a0 = b0; a1 = b1; p = np;
    }
}

extern "C" void kernel_launch(void* const* d_in, const int* in_sizes, int n_in,
                              void* d_out, int out_size) {
    const float4* x = (const float4*)d_in[0];
    float4* y = (float4*)d_out;
    int n = in_sizes[0];            // 67,108,864 floats
    int nf4 = n / 4;                // 16,777,216 float4
    int threads = 256;
    int grid = 148 * 6;             // single wave at ~6 CTAs/SM, grid-stride
    mxq_kernel<<<grid, threads>>>(x, y, nf4);
}

// round 10
// speedup vs baseline: 1.1984x; 1.1984x over previous
#include <cuda_runtime.h>
#include <cuda_bf16.h>
#include <cstdint>

// MX e4m3 quantize-dequantize, block size 32 along rows. (R6 best config +
// launch_bounds occupancy nudge.)
// Coalesced: lane l handles float4 (warpBase + i*32 + l); one MX block =
// 8 consecutive float4s = one aligned 8-lane group at fixed i.
// 4 float4/thread, .cs on loads and stores (measured best cache-hint combo).
// Quantizer: exponent-field bit arithmetic, *s fused into rescale via exact
// power-of-two integer add; x/s via per-block reciprocal + Markstein FMA.
// All rounding steps bit-identical to the reference sequence.

__device__ __forceinline__ float mx_scale(float amax) {
    // sc = bf16(RN(amax/448)) ; RN division via Markstein with r448=RN(1/448)
    const float r448 = 1.0f / 448.0f;
    float q0 = __fmul_rn(amax, r448);
    float dv = __fmaf_rn(__fmaf_rn(-q0, 448.0f, amax), r448, q0);
    float sc = __bfloat162float(__float2bfloat16(dv));
    // s = floor_bf16(sc*256 + 0.5) * 2^-8 (bf16 semantics), 0 -> 1
    float t = sc * 256.0f;                                   // exact exp shift
    float u = __bfloat162float(__float2bfloat16(t + 0.5f));  // bf16 add (RN)
    float s = floorf(u) * 0.00390625f;                       // exact * 2^-8
    return (s == 0.0f) ? 1.0f : s;
}

__device__ __forceinline__ float qdq_e4m3(float x, float s, float r,
                                          uint32_t sB, float c448s) {
    // correctly-rounded d = x / s (Markstein, r = RN(1/s))
    float q0 = __fmul_rn(x, r);
    float d  = __fmaf_rn(__fmaf_rn(-q0, s, x), r, q0);

    uint32_t db  = __float_as_uint(d);
    uint32_t mb  = db & 0x7FFFFFFFu;                       // |d|
    uint32_t peb = max(mb & 0x7F800000u, 0x3C800000u);     // 2^e, e>=-6
    float inv = __uint_as_float(0x80800000u - peb);        // 2^(3-e)
    float ps  = __uint_as_float(peb + sB);                 // 2^(e-3)*s (exact)
    float q = floorf(__fmaf_rn(__uint_as_float(mb), inv, 0.5f)); // half-away
    float outmag = fminf(__fmul_rn(q, ps), c448s);         // == min(q*pout,448)*s
    return __uint_as_float(__float_as_uint(outmag) | (db & 0x80000000u));
}

__global__ void __launch_bounds__(256, 6)
mxq_kernel(const float4* __restrict__ x, float4* __restrict__ y, int nf4) {
    int tid  = blockIdx.x * blockDim.x + threadIdx.x;
    int warp = tid >> 5;
    int lane = tid & 31;
    size_t base = (size_t)warp * 128 + lane;   // warp covers 128 float4 (2 KB)
    if ((size_t)warp * 128 >= (size_t)nf4) return;

    float4 v[4];
#pragma unroll
    for (int i = 0; i < 4; i++) v[i] = __ldcs(x + base + i * 32);

    float s[4], r[4], c448s[4];
    uint32_t sB[4];
#pragma unroll
    for (int i = 0; i < 4; i++) {
        float m = fmaxf(fmaxf(fabsf(v[i].x), fabsf(v[i].y)),
                        fmaxf(fabsf(v[i].z), fabsf(v[i].w)));
        // amax over the 8-lane group owning this MX block
        m = fmaxf(m, __shfl_xor_sync(0xFFFFFFFFu, m, 1));
        m = fmaxf(m, __shfl_xor_sync(0xFFFFFFFFu, m, 2));
        m = fmaxf(m, __shfl_xor_sync(0xFFFFFFFFu, m, 4));
        s[i] = mx_scale(m);
        r[i] = 1.0f / s[i];                            // RN reciprocal per block
        sB[i] = __float_as_uint(s[i]) - 0x41000000u;   // fold *2^-3 * s
        c448s[i] = 448.0f * s[i];                      // exact
    }

#pragma unroll
    for (int i = 0; i < 4; i++) {
        float4 o;
        o.x = qdq_e4m3(v[i].x, s[i], r[i], sB[i], c448s[i]);
        o.y = qdq_e4m3(v[i].y, s[i], r[i], sB[i], c448s[i]);
        o.z = qdq_e4m3(v[i].z, s[i], r[i], sB[i], c448s[i]);
        o.w = qdq_e4m3(v[i].w, s[i], r[i], sB[i], c448s[i]);
        __stcs(y + base + i * 32, o);
    }
}

extern "C" void kernel_launch(void* const* d_in, const int* in_sizes, int n_in,
                              void* d_out, int out_size) {
    const float4* x = (const float4*)d_in[0];
    float4* y = (float4*)d_out;
    int n = in_sizes[0];            // 67,108,864 floats
    int nf4 = n / 4;                // 16,777,216 float4
    int threads = 256;
    int nthreads_total = nf4 / 4;   // 4 float4 per thread
    int grid = (nthreads_total + threads - 1) / threads;
    mxq_kernel<<<grid, threads>>>(x, y, nf4);
}